// round 7
// baseline (speedup 1.0000x reference)
#include <cuda_runtime.h>
#include <stdint.h>

// ---------------- problem constants ----------------------------------------
#define NB   32
#define HH   56
#define WW   56
#define CI   256
#define CO   256
#define HP   58
#define WP   58
#define K9   9
#define NPIX (NB*HH*WW)          // 100352
#define NTILE (NPIX/128)         // 784
#define NKS   72                 // K = 2304 in steps of 32
#define NW_ELEM (K9*CI*CO)       // 589824

#define ROWPAD      48
#define A_BYTES     (64*ROWPAD)              // 3072 (64 pixel rows)
#define B_OFF       A_BYTES
#define STAGE_BYTES (A_BYTES + 256*ROWPAD)   // 3072 + 12288 = 15360
#define NSTAGE      3

// ---------------- device scratch --------------------------------------------
__device__ int   g_act[NB * HP * WP * 64];   // padded s8 acts (4/int), 27.5 MB
__device__ int   g_wt[CO * 576];             // s8 signs, [co][k9*64+cp]
__device__ float g_partial[576];

// ---------------- PTX helpers ------------------------------------------------
__device__ __forceinline__ uint32_t smem_u32(const void* p) {
    uint32_t a;
    asm("{ .reg .u64 t; cvta.to.shared.u64 t, %1; cvt.u32.u64 %0, t; }" : "=r"(a) : "l"(p));
    return a;
}
#define CP_ASYNC16(dst, src) \
    asm volatile("cp.async.cg.shared.global [%0], [%1], 16;" \
        :: "r"(dst), "l"(__cvta_generic_to_global(src)))
#define CP_COMMIT() asm volatile("cp.async.commit_group;" ::: "memory")
#define CP_WAIT(n)  asm volatile("cp.async.wait_group %0;" :: "n"(n) : "memory")

__device__ __forceinline__ void imma16832(int* d, uint32_t a0, uint32_t a1,
                                          uint32_t a2, uint32_t a3,
                                          uint32_t b0, uint32_t b1) {
    asm volatile(
        "mma.sync.aligned.m16n8k32.row.col.s32.s8.s8.s32 "
        "{%0,%1,%2,%3}, {%4,%5,%6,%7}, {%8,%9}, {%0,%1,%2,%3};"
        : "+r"(d[0]), "+r"(d[1]), "+r"(d[2]), "+r"(d[3])
        : "r"(a0), "r"(a1), "r"(a2), "r"(a3), "r"(b0), "r"(b1));
}

// ---------------- 1. partial sums of |W| ------------------------------------
__global__ void __launch_bounds__(256) reduce_absw_1(const float* __restrict__ W) {
    __shared__ float sh[256];
    int b = blockIdx.x, t = threadIdx.x;
    const float* p = W + b * 1024;
    sh[t] = fabsf(p[t]) + fabsf(p[t + 256]) + fabsf(p[t + 512]) + fabsf(p[t + 768]);
    __syncthreads();
    for (int o = 128; o > 0; o >>= 1) { if (t < o) sh[t] += sh[t + o]; __syncthreads(); }
    if (t == 0) g_partial[b] = sh[0];
}

// ---------------- 2. quantize acts -> padded s8 packs ------------------------
__global__ void __launch_bounds__(256) quantize_x(const float* __restrict__ x) {
    int idx = blockIdx.x * 256 + threadIdx.x;          // NB*HP*WP*64
    if (idx >= NB * HP * WP * 64) return;
    int c4 = idx & 63;
    int t  = idx >> 6;
    int wp = t % WP; t /= WP;
    int hp = t % HP;
    int n  = t / HP;
    int pack = 0;
    if (hp >= 1 && hp <= HH && wp >= 1 && wp <= WW) {
        const float4 v = *reinterpret_cast<const float4*>(
            x + (((size_t)(n * HH + (hp - 1)) * WW + (wp - 1)) * CI + c4 * 4));
        int a0 = __float2int_rn(fminf(1.0f, fabsf(v.x)) * 7.0f);
        int a1 = __float2int_rn(fminf(1.0f, fabsf(v.y)) * 7.0f);
        int a2 = __float2int_rn(fminf(1.0f, fabsf(v.z)) * 7.0f);
        int a3 = __float2int_rn(fminf(1.0f, fabsf(v.w)) * 7.0f);
        pack = (a0 & 0xff) | ((a1 & 0xff) << 8) | ((a2 & 0xff) << 16) | ((a3 & 0xff) << 24);
    }
    g_act[idx] = pack;
}

// ---------------- 3. weight signs -> [co][k9][ci] s8 packs -------------------
__global__ void __launch_bounds__(256) wtrans(const float* __restrict__ W) {
    int idx = blockIdx.x * 256 + threadIdx.x;          // 147456 = 576*256
    int co = idx & 255;
    int cp = (idx >> 8) & 63;
    int k9 = idx >> 14;
    int pack = 0;
#pragma unroll
    for (int j = 0; j < 4; j++) {
        float f = W[((size_t)(k9 * CI + cp * 4 + j)) * CO + co];
        int s = (f > 0.0f) - (f < 0.0f);
        pack |= (s & 0xff) << (8 * j);
    }
    g_wt[co * 576 + k9 * 64 + cp] = pack;
}

// ---------------- 4. mixed-CTA conv: IMMA CTAs + dp4a CTAs -------------------
// grid 1568, block 256. Hash (bid + bid>>2)&1 alternates CTA type such that
// wave-1 SM pairs (bid, bid+148) get one of each type.
// type0: IMMA, tile rows 0-63 x co 0-255.  type1: dp4a, tile rows 64-127.
__global__ void __launch_bounds__(256, 2) conv_mixed(const float* __restrict__ bias,
                                                     float* __restrict__ out) {
    __shared__ char  sbuf[NSTAGE * STAGE_BYTES];   // 46080 B
    __shared__ float sbias[256];
    __shared__ float sE;

    const int tid = threadIdx.x;
    const int lane = tid & 31, wid = tid >> 5;
    const int bid = blockIdx.x;
    const int type = (bid + (bid >> 2)) & 1;
    // rank of bid among same-type bids: pattern period 8, 4 of each type
    const int r0tab[8] = {0, 0, 1, 0, 0, 2, 0, 3};
    const int r1tab[8] = {0, 0, 0, 1, 2, 0, 3, 0};
    const int idx = (bid >> 3) * 4 + (type ? r1tab[bid & 7] : r0tab[bid & 7]);
    const int pbase = idx * 128 + type * 64;       // this CTA's 64 pixel rows
    const uint32_t sb = smem_u32(sbuf);

    // ---- E = mean|W| (folded reduce2; sbuf as scratch; 256 threads) ----
    {
        float* red = reinterpret_cast<float*>(sbuf);
        float s = g_partial[tid] + g_partial[tid + 256];
        if (tid < 64) s += g_partial[tid + 512];
        red[tid] = s;
        __syncthreads();
        for (int o = 128; o > 0; o >>= 1) {
            if (tid < o) red[tid] += red[tid + o];
            __syncthreads();
        }
        if (tid == 0) sE = red[0] / (float)NW_ELEM;
        __syncthreads();
    }
    sbias[tid] = bias[tid];

    // ---- producer setup ----
    // threads 0-127: one A 16B chunk (row t>>1, half t&1). all threads: B row t, 2 chunks.
    const int pr = tid >> 1, half = tid & 1;
    const int P = pbase + (pr & 63);
    const int pn = P / 3136;
    const int prm = P - pn * 3136;
    const int ph = prm / 56;
    const int pw = prm - ph * 56;
    const char* aSrc = (const char*)g_act
        + ((size_t)((pn * HP + ph) * WP + pw)) * 256 + half * 16;
    const uint32_t aDst = (uint32_t)((pr & 63) * ROWPAD + half * 16);
    const bool doA = (tid < 128);
    const char* bSrc = (const char*)g_wt + (size_t)tid * 2304;
    const uint32_t bDst = (uint32_t)(B_OFF + tid * ROWPAD);

    // ---- consumer setup ----
    const int mgrp = wid & 1, ngrp = wid >> 1;     // IMMA: 2x4 warp grid
    const uint32_t aoff = (uint32_t)((mgrp * 32 + (lane >> 2)) * ROWPAD + (lane & 3) * 4);
    const uint32_t boff = (uint32_t)(B_OFF + (ngrp * 64 + (lane >> 2)) * ROWPAD + (lane & 3) * 4);

    int acc[64];
#pragma unroll
    for (int j = 0; j < 64; j++) acc[j] = 0;

    // ---- prologue: stages 0,1 ----
#pragma unroll
    for (int ks = 0; ks < NSTAGE - 1; ks++) {
        const int k9 = ks >> 3, cc = ks & 7;
        const int kh = k9 / 3, kw = k9 - kh * 3;
        const uint32_t slot = sb + ks * STAGE_BYTES;
        if (doA) CP_ASYNC16(slot + aDst, aSrc + (kh * WP + kw) * 256 + cc * 32);
        const char* s2 = bSrc + k9 * 256 + cc * 32;
        CP_ASYNC16(slot + bDst, s2);
        CP_ASYNC16(slot + bDst + 16, s2 + 16);
        CP_COMMIT();
    }

    int curSlot = 0, nxtSlot = NSTAGE - 1;
    for (int ks = 0; ks < NKS; ks++) {
        CP_WAIT(1);
        __syncthreads();

        // issue stage ks+2
        {
            const int kn = ks + NSTAGE - 1;
            if (kn < NKS) {
                const int k9 = kn >> 3, cc = kn & 7;
                const int kh = k9 / 3, kw = k9 - kh * 3;
                const uint32_t slot = sb + nxtSlot * STAGE_BYTES;
                if (doA) CP_ASYNC16(slot + aDst, aSrc + (kh * WP + kw) * 256 + cc * 32);
                const char* s2 = bSrc + k9 * 256 + cc * 32;
                CP_ASYNC16(slot + bDst, s2);
                CP_ASYNC16(slot + bDst + 16, s2 + 16);
            }
            CP_COMMIT();
        }

        const char* sc = sbuf + curSlot * STAGE_BYTES;
        if (type == 0) {
            // ---- IMMA: 16 mma per warp ----
            uint32_t af[2][4];
#pragma unroll
            for (int ma = 0; ma < 2; ma++) {
                const char* ab = sc + aoff + ma * (16 * ROWPAD);
                af[ma][0] = *(const uint32_t*)(ab);
                af[ma][1] = *(const uint32_t*)(ab + 8 * ROWPAD);
                af[ma][2] = *(const uint32_t*)(ab + 16);
                af[ma][3] = *(const uint32_t*)(ab + 8 * ROWPAD + 16);
            }
#pragma unroll
            for (int na = 0; na < 8; na++) {
                const char* bb = sc + boff + na * (8 * ROWPAD);
                const uint32_t bf0 = *(const uint32_t*)(bb);
                const uint32_t bf1 = *(const uint32_t*)(bb + 16);
#pragma unroll
                for (int ma = 0; ma < 2; ma++)
                    imma16832(&acc[(ma * 8 + na) * 4], af[ma][0], af[ma][1],
                              af[ma][2], af[ma][3], bf0, bf1);
            }
        } else {
            // ---- dp4a: co = tid, 64 local pixel rows ----
            const int4 w0 = *(const int4*)(sc + B_OFF + tid * ROWPAD);
            const int4 w1 = *(const int4*)(sc + B_OFF + tid * ROWPAD + 16);
#pragma unroll
            for (int px = 0; px < 64; px++) {
                const char* ab = sc + px * ROWPAD;     // broadcast
                const int4 a0 = *(const int4*)(ab);
                const int4 a1 = *(const int4*)(ab + 16);
                int v = acc[px];
                v = __dp4a(a0.x, w0.x, v);
                v = __dp4a(a0.y, w0.y, v);
                v = __dp4a(a0.z, w0.z, v);
                v = __dp4a(a0.w, w0.w, v);
                v = __dp4a(a1.x, w1.x, v);
                v = __dp4a(a1.y, w1.y, v);
                v = __dp4a(a1.z, w1.z, v);
                v = __dp4a(a1.w, w1.w, v);
                acc[px] = v;
            }
        }

        curSlot++; if (curSlot == NSTAGE) curSlot = 0;
        nxtSlot++; if (nxtSlot == NSTAGE) nxtSlot = 0;
    }

    // ---- epilogue ----
    const float scale = sE * (1.0f / 7.0f);
    if (type == 0) {
        const int orow0 = pbase + mgrp * 32 + (lane >> 2);
        const int ocol0 = ngrp * 64 + (lane & 3) * 2;
#pragma unroll
        for (int ma = 0; ma < 2; ma++) {
#pragma unroll
            for (int na = 0; na < 8; na++) {
                const int* a4 = &acc[(ma * 8 + na) * 4];
                const int row = orow0 + ma * 16;
                const int col = ocol0 + na * 8;
                const float b0 = sbias[col];
                const float b1 = sbias[col + 1];
                float2 v0, v1;
                v0.x = (float)a4[0] * scale + b0;
                v0.y = (float)a4[1] * scale + b1;
                v1.x = (float)a4[2] * scale + b0;
                v1.y = (float)a4[3] * scale + b1;
                *reinterpret_cast<float2*>(out + (size_t)row * CO + col) = v0;
                *reinterpret_cast<float2*>(out + (size_t)(row + 8) * CO + col) = v1;
            }
        }
    } else {
        const float bv = sbias[tid];
        size_t obase = (size_t)pbase * CO + tid;
#pragma unroll 8
        for (int px = 0; px < 64; px++) {
            out[obase + (size_t)px * CO] = (float)acc[px] * scale + bv;
        }
    }
}

// ---------------- launch -----------------------------------------------------
extern "C" void kernel_launch(void* const* d_in, const int* in_sizes, int n_in,
                              void* d_out, int out_size) {
    const float* x = (const float*)d_in[0];
    const float* W = (const float*)d_in[1];
    const float* b = (const float*)d_in[2];
    float* out = (float*)d_out;

    int qtot = NB * HP * WP * 64;
    quantize_x<<<(qtot + 255) / 256, 256>>>(x);   // launch 1
    reduce_absw_1<<<576, 256>>>(W);               // launch 2
    wtrans<<<576, 256>>>(W);                      // launch 3
    conv_mixed<<<2 * NTILE, 256>>>(b, out);       // launch 4 (ncu capture slot)
}

// round 8
// speedup vs baseline: 1.5118x; 1.5118x over previous
#include <cuda_runtime.h>
#include <stdint.h>

// ---------------- problem constants ----------------------------------------
#define NB   32
#define HH   56
#define WW   56
#define CI   256
#define CO   256
#define HP   58
#define WP   58
#define K9   9
#define CP4  64
#define TW   28
#define NW_ELEM (K9*CI*CO)       // 589824
#define NKS   72                 // K = 2304 in 32-steps (IMMA kernel)

#define STAGES      3
#define A_BYTES_I   6144         // 128 rows x 48B
#define STAGE_BYTES 12288
#define ROWPAD      48

// ---------------- device scratch --------------------------------------------
__device__ int   g_act[NB * HP * WP * CP4];  // padded s8 act packs, 27.5 MB
__device__ int   g_wtd[K9 * CP4 * CO];       // dp4a layout  [k9][cp][co]
__device__ int   g_wti[CO * 576];            // imma layout  [co][k9*64+cp]
__device__ float g_partial[576];
__device__ float g_E;

// ---------------- streams/events for graph fork-join (host resources) --------
struct SideStream {
    cudaStream_t s;
    cudaEvent_t  fork, join;
    SideStream() {
        cudaStreamCreateWithFlags(&s, cudaStreamNonBlocking);
        cudaEventCreateWithFlags(&fork, cudaEventDisableTiming);
        cudaEventCreateWithFlags(&join, cudaEventDisableTiming);
    }
};
static SideStream g_ss;

// ---------------- PTX helpers ------------------------------------------------
__device__ __forceinline__ uint32_t smem_u32(const void* p) {
    uint32_t a;
    asm("{ .reg .u64 t; cvta.to.shared.u64 t, %1; cvt.u32.u64 %0, t; }" : "=r"(a) : "l"(p));
    return a;
}
#define CP_ASYNC16(dst, src) \
    asm volatile("cp.async.cg.shared.global [%0], [%1], 16;" \
        :: "r"(dst), "l"(__cvta_generic_to_global(src)))
#define CP_COMMIT() asm volatile("cp.async.commit_group;" ::: "memory")
#define CP_WAIT(n)  asm volatile("cp.async.wait_group %0;" :: "n"(n) : "memory")

__device__ __forceinline__ void imma16832(int* d, uint32_t a0, uint32_t a1,
                                          uint32_t a2, uint32_t a3,
                                          uint32_t b0, uint32_t b1) {
    asm volatile(
        "mma.sync.aligned.m16n8k32.row.col.s32.s8.s8.s32 "
        "{%0,%1,%2,%3}, {%4,%5,%6,%7}, {%8,%9}, {%0,%1,%2,%3};"
        : "+r"(d[0]), "+r"(d[1]), "+r"(d[2]), "+r"(d[3])
        : "r"(a0), "r"(a1), "r"(a2), "r"(a3), "r"(b0), "r"(b1));
}

// ---------------- 1a/1b. E = mean|W| -----------------------------------------
__global__ void __launch_bounds__(256) reduce_absw_1(const float* __restrict__ W) {
    __shared__ float sh[256];
    int b = blockIdx.x, t = threadIdx.x;
    const float* p = W + b * 1024;
    sh[t] = fabsf(p[t]) + fabsf(p[t + 256]) + fabsf(p[t + 512]) + fabsf(p[t + 768]);
    __syncthreads();
    for (int o = 128; o > 0; o >>= 1) { if (t < o) sh[t] += sh[t + o]; __syncthreads(); }
    if (t == 0) g_partial[b] = sh[0];
}
__global__ void __launch_bounds__(256) reduce_absw_2() {
    __shared__ float sh[256];
    int t = threadIdx.x;
    float s = g_partial[t] + g_partial[t + 256];
    if (t < 64) s += g_partial[t + 512];
    sh[t] = s;
    __syncthreads();
    for (int o = 128; o > 0; o >>= 1) { if (t < o) sh[t] += sh[t + o]; __syncthreads(); }
    if (t == 0) g_E = sh[0] / (float)NW_ELEM;
}

// ---------------- 2. quantize acts -> padded s8 packs ------------------------
__global__ void __launch_bounds__(256) quantize_x(const float* __restrict__ x) {
    int idx = blockIdx.x * 256 + threadIdx.x;          // NB*HP*WP*64
    if (idx >= NB * HP * WP * CP4) return;
    int c4 = idx & 63;
    int t  = idx >> 6;
    int wp = t % WP; t /= WP;
    int hp = t % HP;
    int n  = t / HP;
    int pack = 0;
    if (hp >= 1 && hp <= HH && wp >= 1 && wp <= WW) {
        const float4 v = *reinterpret_cast<const float4*>(
            x + (((size_t)(n * HH + (hp - 1)) * WW + (wp - 1)) * CI + c4 * 4));
        int a0 = __float2int_rn(fminf(1.0f, fabsf(v.x)) * 7.0f);
        int a1 = __float2int_rn(fminf(1.0f, fabsf(v.y)) * 7.0f);
        int a2 = __float2int_rn(fminf(1.0f, fabsf(v.z)) * 7.0f);
        int a3 = __float2int_rn(fminf(1.0f, fabsf(v.w)) * 7.0f);
        pack = (a0 & 0xff) | ((a1 & 0xff) << 8) | ((a2 & 0xff) << 16) | ((a3 & 0xff) << 24);
    }
    g_act[idx] = pack;
}

// ---------------- 3. weight signs -> both layouts ----------------------------
__global__ void __launch_bounds__(256) wtrans(const float* __restrict__ W) {
    int idx = blockIdx.x * 256 + threadIdx.x;          // 147456 = 576*256
    int co = idx & 255;
    int cp = (idx >> 8) & 63;
    int k9 = idx >> 14;
    int pack = 0;
#pragma unroll
    for (int j = 0; j < 4; j++) {
        float f = W[((size_t)(k9 * CI + cp * 4 + j)) * CO + co];
        int s = (f > 0.0f) - (f < 0.0f);
        pack |= (s & 0xff) << (8 * j);
    }
    g_wtd[(k9 * CP4 + cp) * CO + co] = pack;
    g_wti[co * 576 + k9 * 64 + cp]  = pack;
}

// ---------------- 4a. dp4a direct conv (batches 16..31) ----------------------
// grid (2, 56, 16); block 256 (thread = cout). Proven structure from R1.
__global__ void __launch_bounds__(256) conv_dp4a(const float* __restrict__ bias,
                                                 float* __restrict__ out) {
    const int co = threadIdx.x;
    const int w0 = blockIdx.x * TW;
    const int h  = blockIdx.y;
    const int n  = blockIdx.z + 16;

    __shared__ int s_act[3 * 30 * CP4];  // 23040 B
    {
        int4* s4 = reinterpret_cast<int4*>(s_act);
        const int4* g4 = reinterpret_cast<const int4*>(g_act);
        for (int i = threadIdx.x; i < 3 * 30 * 16; i += 256) {
            int r = i / 480;
            int rem = i - r * 480;
            s4[r * 480 + rem] = g4[((size_t)((n * HP + h + r) * WP) + w0) * 16 + rem];
        }
    }
    __syncthreads();

    int acc[TW];
#pragma unroll
    for (int p = 0; p < TW; p++) acc[p] = 0;

    for (int k9 = 0; k9 < K9; k9++) {
        const int kh = k9 / 3;
        const int kw = k9 - kh * 3;
        const int* __restrict__ srow = s_act + (kh * 30 + kw) * CP4;
        const int* __restrict__ wrow = g_wtd + k9 * CP4 * CO + co;
#pragma unroll 2
        for (int cp = 0; cp < CP4; cp++) {
            const int w = wrow[cp * CO];
            const int* a = srow + cp;
#pragma unroll
            for (int p = 0; p < TW; p++) {
                acc[p] = __dp4a(a[p * CP4], w, acc[p]);
            }
        }
    }

    const float scale = g_E * (1.0f / 7.0f);
    const float bv = bias[co];
    size_t obase = ((size_t)(n * HH + h) * WW + w0) * CO + co;
#pragma unroll
    for (int p = 0; p < TW; p++) {
        out[obase + (size_t)p * CO] = (float)acc[p] * scale + bv;
    }
}

// ---------------- 4b. IMMA implicit GEMM (batches 0..15) ---------------------
// grid (392, 2); block 256 = 8 warps (4M x 2N), warp tile 32x64. From R3 (proven).
__global__ void __launch_bounds__(256, 2) conv_imma(const float* __restrict__ bias,
                                                    float* __restrict__ out) {
    __shared__ char sbuf[STAGES * STAGE_BYTES];        // 36864 B
    __shared__ float sbias[128];

    const int tid = threadIdx.x;
    const int pbase = blockIdx.x * 128;
    const int nbase = blockIdx.y * 128;

    if (tid < 128) sbias[tid] = bias[nbase + tid];

    const int pr = tid >> 1, half = tid & 1;
    const int P = pbase + pr;
    const int pn = P / 3136;
    const int prm = P - pn * 3136;
    const int ph = prm / 56;
    const int pw = prm - ph * 56;
    const char* aBase = (const char*)g_act
        + ((size_t)((pn * HP + ph) * WP + pw)) * 256 + half * 16;
    const char* bBase = (const char*)g_wti + (size_t)(nbase + pr) * 2304 + half * 16;
    const uint32_t dstOff = pr * ROWPAD + half * 16;
    const uint32_t sb = smem_u32(sbuf);

    const int lane = tid & 31, wid = tid >> 5;
    const int mgrp = wid & 3;
    const int ngrp = wid >> 2;
    const uint32_t aoff = (uint32_t)((mgrp * 32 + (lane >> 2)) * ROWPAD + (lane & 3) * 4);
    const uint32_t boff = (uint32_t)((ngrp * 64 + (lane >> 2)) * ROWPAD + (lane & 3) * 4) + A_BYTES_I;

    int acc[2][8][4];
#pragma unroll
    for (int ma = 0; ma < 2; ma++)
#pragma unroll
        for (int na = 0; na < 8; na++)
#pragma unroll
            for (int j = 0; j < 4; j++) acc[ma][na][j] = 0;

#pragma unroll
    for (int ks = 0; ks < STAGES - 1; ks++) {
        const int k9 = ks >> 3, cc = ks & 7;
        const int kh = k9 / 3, kw = k9 - kh * 3;
        const uint32_t slot = sb + ks * STAGE_BYTES;
        CP_ASYNC16(slot + dstOff, aBase + (kh * WP + kw) * 256 + cc * 32);
        CP_ASYNC16(slot + A_BYTES_I + dstOff, bBase + k9 * 256 + cc * 32);
        CP_COMMIT();
    }

    int slotIdx = 0;
    int loadSlot = STAGES - 1;
    for (int ks = 0; ks < NKS; ks++) {
        CP_WAIT(STAGES - 2);
        __syncthreads();

        {
            const int kn = ks + STAGES - 1;
            if (kn < NKS) {
                const int k9 = kn >> 3, cc = kn & 7;
                const int kh = k9 / 3, kw = k9 - kh * 3;
                const uint32_t slot = sb + loadSlot * STAGE_BYTES;
                CP_ASYNC16(slot + dstOff, aBase + (kh * WP + kw) * 256 + cc * 32);
                CP_ASYNC16(slot + A_BYTES_I + dstOff, bBase + k9 * 256 + cc * 32);
            }
            CP_COMMIT();
        }

        const char* s = sbuf + slotIdx * STAGE_BYTES;
        uint32_t af[2][4];
#pragma unroll
        for (int ma = 0; ma < 2; ma++) {
            const char* ab = s + aoff + ma * (16 * ROWPAD);
            af[ma][0] = *(const uint32_t*)(ab);
            af[ma][1] = *(const uint32_t*)(ab + 8 * ROWPAD);
            af[ma][2] = *(const uint32_t*)(ab + 16);
            af[ma][3] = *(const uint32_t*)(ab + 8 * ROWPAD + 16);
        }
        uint32_t bf[8][2];
#pragma unroll
        for (int na = 0; na < 8; na++) {
            const char* bb = s + boff + na * (8 * ROWPAD);
            bf[na][0] = *(const uint32_t*)(bb);
            bf[na][1] = *(const uint32_t*)(bb + 16);
        }
#pragma unroll
        for (int na = 0; na < 8; na++)
#pragma unroll
            for (int ma = 0; ma < 2; ma++)
                imma16832(acc[ma][na], af[ma][0], af[ma][1], af[ma][2], af[ma][3],
                          bf[na][0], bf[na][1]);

        slotIdx++;  if (slotIdx == STAGES) slotIdx = 0;
        loadSlot++; if (loadSlot == STAGES) loadSlot = 0;
    }

    const float scale = g_E * (1.0f / 7.0f);
    const int orow0 = pbase + mgrp * 32 + (lane >> 2);
    const int ocol0 = nbase + ngrp * 64 + (lane & 3) * 2;
#pragma unroll
    for (int ma = 0; ma < 2; ma++) {
#pragma unroll
        for (int na = 0; na < 8; na++) {
            const int row = orow0 + ma * 16;
            const int col = ocol0 + na * 8;
            const float b0 = sbias[col - nbase];
            const float b1 = sbias[col - nbase + 1];
            float2 v0, v1;
            v0.x = (float)acc[ma][na][0] * scale + b0;
            v0.y = (float)acc[ma][na][1] * scale + b1;
            v1.x = (float)acc[ma][na][2] * scale + b0;
            v1.y = (float)acc[ma][na][3] * scale + b1;
            *reinterpret_cast<float2*>(out + (size_t)row * CO + col) = v0;
            *reinterpret_cast<float2*>(out + (size_t)(row + 8) * CO + col) = v1;
        }
    }
}

// ---------------- launch -----------------------------------------------------
extern "C" void kernel_launch(void* const* d_in, const int* in_sizes, int n_in,
                              void* d_out, int out_size) {
    const float* x = (const float*)d_in[0];
    const float* W = (const float*)d_in[1];
    const float* b = (const float*)d_in[2];
    float* out = (float*)d_out;

    // prep (captured stream)
    int qtot = NB * HP * WP * CP4;
    quantize_x<<<(qtot + 255) / 256, 256>>>(x);
    reduce_absw_1<<<576, 256>>>(W);
    reduce_absw_2<<<1, 256>>>();
    wtrans<<<576, 256>>>(W);

    // fork: dp4a conv on side stream, IMMA conv on captured stream (parallel nodes)
    cudaEventRecord(g_ss.fork, 0);
    cudaStreamWaitEvent(g_ss.s, g_ss.fork, 0);
    conv_dp4a<<<dim3(2, 56, 16), 256, 0, g_ss.s>>>(b, out);   // n = 16..31
    cudaEventRecord(g_ss.join, g_ss.s);

    conv_imma<<<dim3(392, 2), 256>>>(b, out);                 // n = 0..15

    // join
    cudaStreamWaitEvent((cudaStream_t)0, g_ss.join, 0);
}

// round 9
// speedup vs baseline: 1.5141x; 1.0015x over previous
#include <cuda_runtime.h>
#include <stdint.h>

// ---------------- problem constants ----------------------------------------
#define NB   32
#define HH   56
#define WW   56
#define CI   256
#define CO   256
#define HP   58
#define WP   58
#define K9   9
#define CP4  64
#define TW   28
#define NW_ELEM (K9*CI*CO)       // 589824
#define NKS   72                 // K = 2304 in 32-steps (IMMA kernel)

#define STAGES      3
#define A_BYTES_I   6144         // 128 rows x 48B
#define STAGE_BYTES 12288
#define ROWPAD      48

// ---------------- device scratch --------------------------------------------
__device__ int   g_act[NB * HP * WP * CP4];  // padded s8 act packs, 27.5 MB
__device__ int   g_wtd[K9 * CP4 * CO];       // dp4a layout  [k9][cp][co]
__device__ int   g_wti[CO * 576];            // imma layout  [co][k9*64+cp]
__device__ float g_partial[576];
__device__ float g_E;

// ---------------- streams/events for graph fork-join (host resources) --------
struct SideStream {
    cudaStream_t s;
    cudaEvent_t  fork, join;
    SideStream() {
        cudaStreamCreateWithFlags(&s, cudaStreamNonBlocking);
        cudaEventCreateWithFlags(&fork, cudaEventDisableTiming);
        cudaEventCreateWithFlags(&join, cudaEventDisableTiming);
    }
};
static SideStream g_ss;

// ---------------- PTX helpers ------------------------------------------------
__device__ __forceinline__ uint32_t smem_u32(const void* p) {
    uint32_t a;
    asm("{ .reg .u64 t; cvta.to.shared.u64 t, %1; cvt.u32.u64 %0, t; }" : "=r"(a) : "l"(p));
    return a;
}
#define CP_ASYNC16(dst, src) \
    asm volatile("cp.async.cg.shared.global [%0], [%1], 16;" \
        :: "r"(dst), "l"(__cvta_generic_to_global(src)))
#define CP_COMMIT() asm volatile("cp.async.commit_group;" ::: "memory")
#define CP_WAIT(n)  asm volatile("cp.async.wait_group %0;" :: "n"(n) : "memory")

__device__ __forceinline__ void imma16832(int* d, uint32_t a0, uint32_t a1,
                                          uint32_t a2, uint32_t a3,
                                          uint32_t b0, uint32_t b1) {
    asm volatile(
        "mma.sync.aligned.m16n8k32.row.col.s32.s8.s8.s32 "
        "{%0,%1,%2,%3}, {%4,%5,%6,%7}, {%8,%9}, {%0,%1,%2,%3};"
        : "+r"(d[0]), "+r"(d[1]), "+r"(d[2]), "+r"(d[3])
        : "r"(a0), "r"(a1), "r"(a2), "r"(a3), "r"(b0), "r"(b1));
}

// ---------------- 1a/1b. E = mean|W| -----------------------------------------
__global__ void __launch_bounds__(256) reduce_absw_1(const float* __restrict__ W) {
    __shared__ float sh[256];
    int b = blockIdx.x, t = threadIdx.x;
    const float* p = W + b * 1024;
    sh[t] = fabsf(p[t]) + fabsf(p[t + 256]) + fabsf(p[t + 512]) + fabsf(p[t + 768]);
    __syncthreads();
    for (int o = 128; o > 0; o >>= 1) { if (t < o) sh[t] += sh[t + o]; __syncthreads(); }
    if (t == 0) g_partial[b] = sh[0];
}
__global__ void __launch_bounds__(256) reduce_absw_2() {
    __shared__ float sh[256];
    int t = threadIdx.x;
    float s = g_partial[t] + g_partial[t + 256];
    if (t < 64) s += g_partial[t + 512];
    sh[t] = s;
    __syncthreads();
    for (int o = 128; o > 0; o >>= 1) { if (t < o) sh[t] += sh[t + o]; __syncthreads(); }
    if (t == 0) g_E = sh[0] / (float)NW_ELEM;
}

// ---------------- 2. quantize acts -> padded s8 packs ------------------------
__global__ void __launch_bounds__(256) quantize_x(const float* __restrict__ x) {
    int idx = blockIdx.x * 256 + threadIdx.x;          // NB*HP*WP*64
    if (idx >= NB * HP * WP * CP4) return;
    int c4 = idx & 63;
    int t  = idx >> 6;
    int wp = t % WP; t /= WP;
    int hp = t % HP;
    int n  = t / HP;
    int pack = 0;
    if (hp >= 1 && hp <= HH && wp >= 1 && wp <= WW) {
        const float4 v = *reinterpret_cast<const float4*>(
            x + (((size_t)(n * HH + (hp - 1)) * WW + (wp - 1)) * CI + c4 * 4));
        int a0 = __float2int_rn(fminf(1.0f, fabsf(v.x)) * 7.0f);
        int a1 = __float2int_rn(fminf(1.0f, fabsf(v.y)) * 7.0f);
        int a2 = __float2int_rn(fminf(1.0f, fabsf(v.z)) * 7.0f);
        int a3 = __float2int_rn(fminf(1.0f, fabsf(v.w)) * 7.0f);
        pack = (a0 & 0xff) | ((a1 & 0xff) << 8) | ((a2 & 0xff) << 16) | ((a3 & 0xff) << 24);
    }
    g_act[idx] = pack;
}

// ---------------- 3. weight signs -> both layouts ----------------------------
__global__ void __launch_bounds__(256) wtrans(const float* __restrict__ W) {
    int idx = blockIdx.x * 256 + threadIdx.x;          // 147456 = 576*256
    int co = idx & 255;
    int cp = (idx >> 8) & 63;
    int k9 = idx >> 14;
    int pack = 0;
#pragma unroll
    for (int j = 0; j < 4; j++) {
        float f = W[((size_t)(k9 * CI + cp * 4 + j)) * CO + co];
        int s = (f > 0.0f) - (f < 0.0f);
        pack |= (s & 0xff) << (8 * j);
    }
    g_wtd[(k9 * CP4 + cp) * CO + co] = pack;
    g_wti[co * 576 + k9 * 64 + cp]  = pack;
}

// ---------------- 4a. dp4a direct conv (batches 16..31) ----------------------
// grid (2, 56, 16); block 256 (thread = cout). Proven structure from R1.
__global__ void __launch_bounds__(256) conv_dp4a(const float* __restrict__ bias,
                                                 float* __restrict__ out) {
    const int co = threadIdx.x;
    const int w0 = blockIdx.x * TW;
    const int h  = blockIdx.y;
    const int n  = blockIdx.z + 16;

    __shared__ int s_act[3 * 30 * CP4];  // 23040 B
    {
        int4* s4 = reinterpret_cast<int4*>(s_act);
        const int4* g4 = reinterpret_cast<const int4*>(g_act);
        for (int i = threadIdx.x; i < 3 * 30 * 16; i += 256) {
            int r = i / 480;
            int rem = i - r * 480;
            s4[r * 480 + rem] = g4[((size_t)((n * HP + h + r) * WP) + w0) * 16 + rem];
        }
    }
    __syncthreads();

    int acc[TW];
#pragma unroll
    for (int p = 0; p < TW; p++) acc[p] = 0;

    for (int k9 = 0; k9 < K9; k9++) {
        const int kh = k9 / 3;
        const int kw = k9 - kh * 3;
        const int* __restrict__ srow = s_act + (kh * 30 + kw) * CP4;
        const int* __restrict__ wrow = g_wtd + k9 * CP4 * CO + co;
#pragma unroll 2
        for (int cp = 0; cp < CP4; cp++) {
            const int w = wrow[cp * CO];
            const int* a = srow + cp;
#pragma unroll
            for (int p = 0; p < TW; p++) {
                acc[p] = __dp4a(a[p * CP4], w, acc[p]);
            }
        }
    }

    const float scale = g_E * (1.0f / 7.0f);
    const float bv = bias[co];
    size_t obase = ((size_t)(n * HH + h) * WW + w0) * CO + co;
#pragma unroll
    for (int p = 0; p < TW; p++) {
        out[obase + (size_t)p * CO] = (float)acc[p] * scale + bv;
    }
}

// ---------------- 4b. IMMA implicit GEMM (batches 0..15) ---------------------
// grid (392, 2); block 256 = 8 warps (4M x 2N), warp tile 32x64. From R3 (proven).
__global__ void __launch_bounds__(256, 2) conv_imma(const float* __restrict__ bias,
                                                    float* __restrict__ out) {
    __shared__ char sbuf[STAGES * STAGE_BYTES];        // 36864 B
    __shared__ float sbias[128];

    const int tid = threadIdx.x;
    const int pbase = blockIdx.x * 128;
    const int nbase = blockIdx.y * 128;

    if (tid < 128) sbias[tid] = bias[nbase + tid];

    const int pr = tid >> 1, half = tid & 1;
    const int P = pbase + pr;
    const int pn = P / 3136;
    const int prm = P - pn * 3136;
    const int ph = prm / 56;
    const int pw = prm - ph * 56;
    const char* aBase = (const char*)g_act
        + ((size_t)((pn * HP + ph) * WP + pw)) * 256 + half * 16;
    const char* bBase = (const char*)g_wti + (size_t)(nbase + pr) * 2304 + half * 16;
    const uint32_t dstOff = pr * ROWPAD + half * 16;
    const uint32_t sb = smem_u32(sbuf);

    const int lane = tid & 31, wid = tid >> 5;
    const int mgrp = wid & 3;
    const int ngrp = wid >> 2;
    const uint32_t aoff = (uint32_t)((mgrp * 32 + (lane >> 2)) * ROWPAD + (lane & 3) * 4);
    const uint32_t boff = (uint32_t)((ngrp * 64 + (lane >> 2)) * ROWPAD + (lane & 3) * 4) + A_BYTES_I;

    int acc[2][8][4];
#pragma unroll
    for (int ma = 0; ma < 2; ma++)
#pragma unroll
        for (int na = 0; na < 8; na++)
#pragma unroll
            for (int j = 0; j < 4; j++) acc[ma][na][j] = 0;

#pragma unroll
    for (int ks = 0; ks < STAGES - 1; ks++) {
        const int k9 = ks >> 3, cc = ks & 7;
        const int kh = k9 / 3, kw = k9 - kh * 3;
        const uint32_t slot = sb + ks * STAGE_BYTES;
        CP_ASYNC16(slot + dstOff, aBase + (kh * WP + kw) * 256 + cc * 32);
        CP_ASYNC16(slot + A_BYTES_I + dstOff, bBase + k9 * 256 + cc * 32);
        CP_COMMIT();
    }

    int slotIdx = 0;
    int loadSlot = STAGES - 1;
    for (int ks = 0; ks < NKS; ks++) {
        CP_WAIT(STAGES - 2);
        __syncthreads();

        {
            const int kn = ks + STAGES - 1;
            if (kn < NKS) {
                const int k9 = kn >> 3, cc = kn & 7;
                const int kh = k9 / 3, kw = k9 - kh * 3;
                const uint32_t slot = sb + loadSlot * STAGE_BYTES;
                CP_ASYNC16(slot + dstOff, aBase + (kh * WP + kw) * 256 + cc * 32);
                CP_ASYNC16(slot + A_BYTES_I + dstOff, bBase + k9 * 256 + cc * 32);
            }
            CP_COMMIT();
        }

        const char* s = sbuf + slotIdx * STAGE_BYTES;
        uint32_t af[2][4];
#pragma unroll
        for (int ma = 0; ma < 2; ma++) {
            const char* ab = s + aoff + ma * (16 * ROWPAD);
            af[ma][0] = *(const uint32_t*)(ab);
            af[ma][1] = *(const uint32_t*)(ab + 8 * ROWPAD);
            af[ma][2] = *(const uint32_t*)(ab + 16);
            af[ma][3] = *(const uint32_t*)(ab + 8 * ROWPAD + 16);
        }
        uint32_t bf[8][2];
#pragma unroll
        for (int na = 0; na < 8; na++) {
            const char* bb = s + boff + na * (8 * ROWPAD);
            bf[na][0] = *(const uint32_t*)(bb);
            bf[na][1] = *(const uint32_t*)(bb + 16);
        }
#pragma unroll
        for (int na = 0; na < 8; na++)
#pragma unroll
            for (int ma = 0; ma < 2; ma++)
                imma16832(acc[ma][na], af[ma][0], af[ma][1], af[ma][2], af[ma][3],
                          bf[na][0], bf[na][1]);

        slotIdx++;  if (slotIdx == STAGES) slotIdx = 0;
        loadSlot++; if (loadSlot == STAGES) loadSlot = 0;
    }

    const float scale = g_E * (1.0f / 7.0f);
    const int orow0 = pbase + mgrp * 32 + (lane >> 2);
    const int ocol0 = nbase + ngrp * 64 + (lane & 3) * 2;
#pragma unroll
    for (int ma = 0; ma < 2; ma++) {
#pragma unroll
        for (int na = 0; na < 8; na++) {
            const int row = orow0 + ma * 16;
            const int col = ocol0 + na * 8;
            const float b0 = sbias[col - nbase];
            const float b1 = sbias[col - nbase + 1];
            float2 v0, v1;
            v0.x = (float)acc[ma][na][0] * scale + b0;
            v0.y = (float)acc[ma][na][1] * scale + b1;
            v1.x = (float)acc[ma][na][2] * scale + b0;
            v1.y = (float)acc[ma][na][3] * scale + b1;
            *reinterpret_cast<float2*>(out + (size_t)row * CO + col) = v0;
            *reinterpret_cast<float2*>(out + (size_t)(row + 8) * CO + col) = v1;
        }
    }
}

// ---------------- launch -----------------------------------------------------
extern "C" void kernel_launch(void* const* d_in, const int* in_sizes, int n_in,
                              void* d_out, int out_size) {
    const float* x = (const float*)d_in[0];
    const float* W = (const float*)d_in[1];
    const float* b = (const float*)d_in[2];
    float* out = (float*)d_out;

    // prep (captured stream)
    int qtot = NB * HP * WP * CP4;
    quantize_x<<<(qtot + 255) / 256, 256>>>(x);
    reduce_absw_1<<<576, 256>>>(W);
    reduce_absw_2<<<1, 256>>>();
    wtrans<<<576, 256>>>(W);

    // fork: dp4a conv on side stream, IMMA conv on captured stream (parallel nodes)
    cudaEventRecord(g_ss.fork, 0);
    cudaStreamWaitEvent(g_ss.s, g_ss.fork, 0);
    conv_dp4a<<<dim3(2, 56, 16), 256, 0, g_ss.s>>>(b, out);   // n = 16..31
    cudaEventRecord(g_ss.join, g_ss.s);

    conv_imma<<<dim3(392, 2), 256>>>(b, out);                 // n = 0..15

    // join
    cudaStreamWaitEvent((cudaStream_t)0, g_ss.join, 0);
}